// round 12
// baseline (speedup 1.0000x reference)
#include <cuda_runtime.h>
#include <cuda_fp16.h>
#include <cstdint>

#define DT 0.01f

constexpr int B    = 2;
constexpr int N    = 20000;
constexpr int D    = 64;
constexpr int E    = 320000;
constexpr int ND   = N * D;          // floats per batch       = 1,280,000
constexpr int ND4  = ND / 4;         // float4s per batch      = 320,000
constexpr int TOT4 = B * ND4;        // float4s per (B,N,D)    = 640,000
constexpr int QH4  = B * ND / 8;     // uint4 count of fp16 q  = 320,000

// Scratch (allocation-free rule: __device__ globals, zero-initialized at load;
// finalize_kernel resets acc/deg for graph replays; g_qh4 is overwritten each launch).
__device__ uint4 g_acc[B * ND / 8];  // fp16 accumulator: 8 halves per uint4 (5.12 MB)
__device__ uint4 g_qh4[QH4];         // fp16 copy of q: 8 halves per uint4 (5.12 MB)
__device__ int   g_deg[N];           // in-degree per node (shared across batch)

__device__ __forceinline__ unsigned int h2_as_u32(__half2 h) {
    return *reinterpret_cast<unsigned int*>(&h);
}

__device__ __forceinline__ void red4_f16x2(void* p, unsigned int a, unsigned int b,
                                           unsigned int c, unsigned int d) {
    asm volatile("red.global.add.noftz.v4.f16x2 [%0], {%1, %2, %3, %4};"
                 :: "l"(p), "r"(a), "r"(b), "r"(c), "r"(d)
                 : "memory");
}

// ---------------------------------------------------------------------------
// K0: convert q (fp32) to a packed fp16 copy, once per launch.  This halves
// the per-edge gather traffic in K1 and removes the conversion from the
// E*16-thread hot loop.
// ---------------------------------------------------------------------------
__global__ void convert_kernel(const float* __restrict__ q) {
    int gid = blockIdx.x * blockDim.x + threadIdx.x;
    if (gid >= QH4) return;
    const float4* q4 = reinterpret_cast<const float4*>(q);
    float4 a = __ldg(&q4[gid * 2]);
    float4 b = __ldg(&q4[gid * 2 + 1]);
    uint4 o;
    o.x = h2_as_u32(__float22half2_rn(make_float2(a.x, a.y)));
    o.y = h2_as_u32(__float22half2_rn(make_float2(a.z, a.w)));
    o.z = h2_as_u32(__float22half2_rn(make_float2(b.x, b.y)));
    o.w = h2_as_u32(__float22half2_rn(make_float2(b.z, b.w)));
    g_qh4[gid] = o;
}

// ---------------------------------------------------------------------------
// K1: edge-parallel scatter.  16 threads/edge; thread t: half=t>>3 (batch),
// k=t&7 (dims [8k, 8k+8)).  Gather 16B of fp16 q[src], ONE fire-and-forget
// 16B RED per thread.  Pure TLP — runs at the LTS cap.
// Only q[src] is gathered; the q[dst] term is folded into finalize as deg*q.
// ---------------------------------------------------------------------------
__global__ void edge_kernel(const int2* __restrict__ edges) {
    int gid = blockIdx.x * blockDim.x + threadIdx.x;
    int e   = gid >> 4;
    if (e >= E) return;
    int t    = gid & 15;
    int half = t >> 3;          // batch
    int k    = t & 7;           // 8-dim chunk

    int2 ed = __ldg(&edges[e]);

    uint4 v = g_qh4[half * (ND / 8) + ed.x * 8 + k];
    uint4* dstp = &g_acc[half * (ND / 8) + ed.y * 8 + k];
    red4_f16x2(dstp, v.x, v.y, v.z, v.w);

    if (t == 0) atomicAdd(&g_deg[ed.y], 1);
}

// ---------------------------------------------------------------------------
// K2: fused epilogue, WARP PER NODE (640k threads).  lane: half=lane>>4
// (batch), c=lane&15 (float4 chunk).  Both batch elements of node n live in
// one warp, so the deg read -> reset is warp-synchronous.  msg = deg*q - acc;
// symplectic update; Kalman fix on node 0.  Resets acc and deg for replay.
// ---------------------------------------------------------------------------
__global__ void finalize_kernel(const float* __restrict__ q, const float* __restrict__ p,
                                const float* __restrict__ obs, const float* __restrict__ kg,
                                float* __restrict__ out) {
    int gid = blockIdx.x * blockDim.x + threadIdx.x;   // [0, N*32)
    if (gid >= N * 32) return;
    int n    = gid >> 5;
    int lane = gid & 31;
    int half = lane >> 4;        // batch
    int c    = lane & 15;        // float4 chunk (4 dims)

    const float4* q4 = reinterpret_cast<const float4*>(q);
    const float4* p4 = reinterpret_cast<const float4*>(p);
    uint2* acc2 = reinterpret_cast<uint2*>(g_acc);      // 4 halves per uint2

    int i = half * ND4 + n * 16 + c;    // float4 index; also uint2 index into acc

    float4 qq = q4[i];
    float4 pp = p4[i];
    uint2  r  = acc2[i];
    int  degi = g_deg[n];               // broadcast within warp
    __syncwarp();
    if (lane == 0) g_deg[n] = 0;        // reset after all lanes read
    acc2[i] = make_uint2(0u, 0u);       // reset scratch for next replay

    float dg = (float)degi;
    __half2 ra = *reinterpret_cast<__half2*>(&r.x);
    __half2 rb = *reinterpret_cast<__half2*>(&r.y);
    float2 sa = __half22float2(ra);
    float2 sb = __half22float2(rb);

    // msg = deg * q[n] - sum q[src]
    float mx = dg*qq.x - sa.x, my = dg*qq.y - sa.y, mz = dg*qq.z - sb.x, mw = dg*qq.w - sb.y;

    // q_new = q + DT*(p + 0.5*DT*msg) ; p_new = p + DT*msg
    float qnx = qq.x + DT*(pp.x + 0.5f*DT*mx), qny = qq.y + DT*(pp.y + 0.5f*DT*my);
    float qnz = qq.z + DT*(pp.z + 0.5f*DT*mz), qnw = qq.w + DT*(pp.w + 0.5f*DT*mw);
    float pnx = pp.x + DT*mx, pny = pp.y + DT*my, pnz = pp.z + DT*mz, pnw = pp.w + DT*mw;

    if (n == 0) {
        const float4* obs4 = reinterpret_cast<const float4*>(obs);
        const float4* kg4  = reinterpret_cast<const float4*>(kg);
        float4 ob = obs4[half * 16 + c];   // observations[half]
        float4 kq = kg4[c];                // kalman_gain[0:D]
        float4 kp = kg4[16 + c];           // kalman_gain[D:2D]

        float ix = ob.x - qnx, iy = ob.y - qny, iz = ob.z - qnz, iw = ob.w - qnw;
        qnx += kq.x*ix;  qny += kq.y*iy;  qnz += kq.z*iz;  qnw += kq.w*iw;
        pnx += kp.x*ix;  pny += kp.y*iy;  pnz += kp.z*iz;  pnw += kp.w*iw;
    }

    float4* o4 = reinterpret_cast<float4*>(out);
    o4[i]        = make_float4(qnx, qny, qnz, qnw);   // q_new
    o4[TOT4 + i] = make_float4(pnx, pny, pnz, pnw);   // p_new
}

extern "C" void kernel_launch(void* const* d_in, const int* in_sizes, int n_in,
                              void* d_out, int out_size) {
    const float* q   = (const float*)d_in[0];   // node_q  (B,N,D) f32
    const float* p   = (const float*)d_in[1];   // node_p  (B,N,D) f32
    const float* obs = (const float*)d_in[2];   // observations (B,D) f32
    const float* kg  = (const float*)d_in[3];   // kalman_gain (2D,) f32
    const int2*  edg = (const int2*)d_in[4];    // edges (E,2) i32
    float* out = (float*)d_out;

    convert_kernel<<<(QH4 + 255) / 256, 256>>>(q);
    edge_kernel<<<(E * 16 + 255) / 256, 256>>>(edg);
    finalize_kernel<<<(N * 32 + 255) / 256, 256>>>(q, p, obs, kg, out);
}

// round 13
// speedup vs baseline: 1.0231x; 1.0231x over previous
#include <cuda_runtime.h>
#include <cuda_fp16.h>
#include <cstdint>

#define DT 0.01f

constexpr int B    = 2;
constexpr int N    = 20000;
constexpr int D    = 64;
constexpr int E    = 320000;
constexpr int ND   = N * D;          // floats per batch       = 1,280,000
constexpr int ND4  = ND / 4;         // float4s per batch      = 320,000
constexpr int TOT4 = B * ND4;        // float4s per (B,N,D)    = 640,000

// Scratch (allocation-free rule: __device__ globals, zero-initialized at load;
// finalize_kernel resets acc/deg for graph replays).
__device__ uint4 g_acc[B * ND / 8];  // fp16 accumulator: 8 halves per uint4 (5.12 MB)
__device__ int   g_deg[N];           // in-degree per node (shared across batch)

__device__ __forceinline__ unsigned int h2_as_u32(__half2 h) {
    return *reinterpret_cast<unsigned int*>(&h);
}

__device__ __forceinline__ void red4_f16x2(void* p, unsigned int a, unsigned int b,
                                           unsigned int c, unsigned int d) {
    asm volatile("red.global.add.noftz.v4.f16x2 [%0], {%1, %2, %3, %4};"
                 :: "l"(p), "r"(a), "r"(b), "r"(c), "r"(d)
                 : "memory");
}

// ---------------------------------------------------------------------------
// K1: edge-parallel scatter (R10 version — measured 17.0 us).  16 threads per
// edge; thread t: half=t>>3 (batch), k=t&7 (dims [8k, 8k+8)).  Gather 32B of
// q[src] fp32, convert to fp16 in-thread, ONE fire-and-forget 16B RED.
// Pure TLP.  Only q[src] is gathered; q[dst] folds into finalize as deg*q.
// ---------------------------------------------------------------------------
__global__ void edge_kernel(const int2* __restrict__ edges, const float* __restrict__ q) {
    int gid = blockIdx.x * blockDim.x + threadIdx.x;
    int e   = gid >> 4;
    if (e >= E) return;
    int t    = gid & 15;
    int half = t >> 3;          // batch
    int k    = t & 7;           // 8-dim chunk

    int2 ed = __ldg(&edges[e]);

    const float4* q4 = reinterpret_cast<const float4*>(q);
    int base = half * ND4 + ed.x * 16 + k * 2;
    float4 a = __ldg(&q4[base]);
    float4 b = __ldg(&q4[base + 1]);

    __half2 h0 = __float22half2_rn(make_float2(a.x, a.y));
    __half2 h1 = __float22half2_rn(make_float2(a.z, a.w));
    __half2 h2 = __float22half2_rn(make_float2(b.x, b.y));
    __half2 h3 = __float22half2_rn(make_float2(b.z, b.w));

    uint4* dstp = &g_acc[half * (ND / 8) + ed.y * 8 + k];
    red4_f16x2(dstp, h2_as_u32(h0), h2_as_u32(h1), h2_as_u32(h2), h2_as_u32(h3));

    if (t == 0) atomicAdd(&g_deg[ed.y], 1);
}

// ---------------------------------------------------------------------------
// K2: fused epilogue, WARP PER NODE (640k threads).  lane: half=lane>>4
// (batch), c=lane&15 (float4 chunk).  Both batch elements of node n live in
// one warp, so the deg read -> reset is warp-synchronous.  msg = deg*q - acc;
// symplectic update; Kalman fix on node 0.  Resets acc and deg for replay.
// ---------------------------------------------------------------------------
__global__ void finalize_kernel(const float* __restrict__ q, const float* __restrict__ p,
                                const float* __restrict__ obs, const float* __restrict__ kg,
                                float* __restrict__ out) {
    int gid = blockIdx.x * blockDim.x + threadIdx.x;   // [0, N*32)
    if (gid >= N * 32) return;
    int n    = gid >> 5;
    int lane = gid & 31;
    int half = lane >> 4;        // batch
    int c    = lane & 15;        // float4 chunk (4 dims)

    const float4* q4 = reinterpret_cast<const float4*>(q);
    const float4* p4 = reinterpret_cast<const float4*>(p);
    uint2* acc2 = reinterpret_cast<uint2*>(g_acc);      // 4 halves per uint2

    int i = half * ND4 + n * 16 + c;    // float4 index; also uint2 index into acc

    float4 qq = q4[i];
    float4 pp = p4[i];
    uint2  r  = acc2[i];
    int  degi = g_deg[n];               // broadcast within warp
    __syncwarp();
    if (lane == 0) g_deg[n] = 0;        // reset after all lanes read
    acc2[i] = make_uint2(0u, 0u);       // reset scratch for next replay

    float dg = (float)degi;
    __half2 ra = *reinterpret_cast<__half2*>(&r.x);
    __half2 rb = *reinterpret_cast<__half2*>(&r.y);
    float2 sa = __half22float2(ra);
    float2 sb = __half22float2(rb);

    // msg = deg * q[n] - sum q[src]
    float mx = dg*qq.x - sa.x, my = dg*qq.y - sa.y, mz = dg*qq.z - sb.x, mw = dg*qq.w - sb.y;

    // q_new = q + DT*(p + 0.5*DT*msg) ; p_new = p + DT*msg
    float qnx = qq.x + DT*(pp.x + 0.5f*DT*mx), qny = qq.y + DT*(pp.y + 0.5f*DT*my);
    float qnz = qq.z + DT*(pp.z + 0.5f*DT*mz), qnw = qq.w + DT*(pp.w + 0.5f*DT*mw);
    float pnx = pp.x + DT*mx, pny = pp.y + DT*my, pnz = pp.z + DT*mz, pnw = pp.w + DT*mw;

    if (n == 0) {
        const float4* obs4 = reinterpret_cast<const float4*>(obs);
        const float4* kg4  = reinterpret_cast<const float4*>(kg);
        float4 ob = obs4[half * 16 + c];   // observations[half]
        float4 kq = kg4[c];                // kalman_gain[0:D]
        float4 kp = kg4[16 + c];           // kalman_gain[D:2D]

        float ix = ob.x - qnx, iy = ob.y - qny, iz = ob.z - qnz, iw = ob.w - qnw;
        qnx += kq.x*ix;  qny += kq.y*iy;  qnz += kq.z*iz;  qnw += kq.w*iw;
        pnx += kp.x*ix;  pny += kp.y*iy;  pnz += kp.z*iz;  pnw += kp.w*iw;
    }

    float4* o4 = reinterpret_cast<float4*>(out);
    o4[i]        = make_float4(qnx, qny, qnz, qnw);   // q_new
    o4[TOT4 + i] = make_float4(pnx, pny, pnz, pnw);   // p_new
}

extern "C" void kernel_launch(void* const* d_in, const int* in_sizes, int n_in,
                              void* d_out, int out_size) {
    const float* q   = (const float*)d_in[0];   // node_q  (B,N,D) f32
    const float* p   = (const float*)d_in[1];   // node_p  (B,N,D) f32
    const float* obs = (const float*)d_in[2];   // observations (B,D) f32
    const float* kg  = (const float*)d_in[3];   // kalman_gain (2D,) f32
    const int2*  edg = (const int2*)d_in[4];    // edges (E,2) i32
    float* out = (float*)d_out;

    edge_kernel<<<(E * 16 + 255) / 256, 256>>>(edg, q);
    finalize_kernel<<<(N * 32 + 255) / 256, 256>>>(q, p, obs, kg, out);
}

// round 14
// speedup vs baseline: 1.1172x; 1.0921x over previous
#include <cuda_runtime.h>
#include <cuda_fp16.h>
#include <cstdint>

#define DT 0.01f

constexpr int B    = 2;
constexpr int N    = 20000;
constexpr int D    = 64;
constexpr int E    = 320000;
constexpr int ND   = N * D;          // floats per batch       = 1,280,000
constexpr int ND4  = ND / 4;         // float4s per batch      = 320,000
constexpr int TOT4 = B * ND4;        // float4s per (B,N,D)    = 640,000

// Scratch (allocation-free rule: __device__ globals, zero-initialized at load;
// finalize_kernel resets acc/deg for graph replays).
__device__ uint4 g_acc[B * ND / 8];  // fp16 accumulator: 8 halves per uint4 (5.12 MB)
__device__ int   g_deg[N];           // in-degree per node (shared across batch)

__device__ __forceinline__ unsigned int h2_as_u32(__half2 h) {
    return *reinterpret_cast<unsigned int*>(&h);
}

__device__ __forceinline__ void red4_f16x2(void* p, unsigned int a, unsigned int b,
                                           unsigned int c, unsigned int d) {
    asm volatile("red.global.add.noftz.v4.f16x2 [%0], {%1, %2, %3, %4};"
                 :: "l"(p), "r"(a), "r"(b), "r"(c), "r"(d)
                 : "memory");
}

__device__ __forceinline__ void red_s32(int* p, int v) {
    asm volatile("red.global.add.s32 [%0], %1;" :: "l"(p), "r"(v) : "memory");
}

// ---------------------------------------------------------------------------
// K1: edge-parallel scatter (R10 version).  16 threads per edge; thread t:
// half=t>>3 (batch), k=t&7 (dims [8k, 8k+8)).  Gather 32B of q[src] fp32,
// convert to fp16 in-thread, ONE fire-and-forget 16B RED.  Pure TLP.
// Only q[src] is gathered; q[dst] folds into finalize as deg*q.
// ---------------------------------------------------------------------------
__global__ void edge_kernel(const int2* __restrict__ edges, const float* __restrict__ q) {
    int gid = blockIdx.x * blockDim.x + threadIdx.x;
    int e   = gid >> 4;
    if (e >= E) return;
    int t    = gid & 15;
    int half = t >> 3;          // batch
    int k    = t & 7;           // 8-dim chunk

    int2 ed = __ldg(&edges[e]);

    const float4* q4 = reinterpret_cast<const float4*>(q);
    int base = half * ND4 + ed.x * 16 + k * 2;
    float4 a = __ldg(&q4[base]);
    float4 b = __ldg(&q4[base + 1]);

    __half2 h0 = __float22half2_rn(make_float2(a.x, a.y));
    __half2 h1 = __float22half2_rn(make_float2(a.z, a.w));
    __half2 h2 = __float22half2_rn(make_float2(b.x, b.y));
    __half2 h3 = __float22half2_rn(make_float2(b.z, b.w));

    uint4* dstp = &g_acc[half * (ND / 8) + ed.y * 8 + k];
    red4_f16x2(dstp, h2_as_u32(h0), h2_as_u32(h1), h2_as_u32(h2), h2_as_u32(h3));

    if (t == 0) red_s32(&g_deg[ed.y], 1);   // no-return RED, not returning atomic
}

// ---------------------------------------------------------------------------
// K2: fused epilogue (R10 mapping: thread per (node, chunk), BOTH batches per
// thread, so the deg read -> reset is same-warp-ordered).  msg = deg*q - acc;
// symplectic update; Kalman fix on node 0.  Resets acc and deg for replay.
// OUT writes use __stcs (streaming): out is write-once, never read — keep it
// out of L2 so q/p/acc/edges stay resident across graph replays.
// ---------------------------------------------------------------------------
__global__ void finalize_kernel(const float* __restrict__ q, const float* __restrict__ p,
                                const float* __restrict__ obs, const float* __restrict__ kg,
                                float* __restrict__ out) {
    int gid = blockIdx.x * blockDim.x + threadIdx.x;   // [0, ND4)
    if (gid >= ND4) return;
    int c = gid & 15;            // float4 chunk (4 dims)
    int n = gid >> 4;

    const float4* q4 = reinterpret_cast<const float4*>(q);
    const float4* p4 = reinterpret_cast<const float4*>(p);
    uint2* acc2 = reinterpret_cast<uint2*>(g_acc);      // 4 halves per uint2

    int i0 = n * 16 + c;            // batch 0 element (float4 units)
    int i1 = ND4 + n * 16 + c;      // batch 1 element

    float4 qq0 = q4[i0],  qq1 = q4[i1];
    float4 pp0 = p4[i0],  pp1 = p4[i1];

    uint2 r0 = acc2[i0];
    uint2 r1 = acc2[i1];
    int  degi = g_deg[n];           // all 16 lanes of node n are in one warp
    float dg  = (float)degi;

    acc2[i0] = make_uint2(0u, 0u);  // reset scratch for next replay
    acc2[i1] = make_uint2(0u, 0u);
    if (c == 0) g_deg[n] = 0;       // after the same-warp reads above

    __half2 r0a = *reinterpret_cast<__half2*>(&r0.x);
    __half2 r0b = *reinterpret_cast<__half2*>(&r0.y);
    __half2 r1a = *reinterpret_cast<__half2*>(&r1.x);
    __half2 r1b = *reinterpret_cast<__half2*>(&r1.y);
    float2 s0a = __half22float2(r0a);
    float2 s0b = __half22float2(r0b);
    float2 s1a = __half22float2(r1a);
    float2 s1b = __half22float2(r1b);

    // msg = deg * q[n] - sum q[src]
    float m0x = dg*qq0.x - s0a.x, m0y = dg*qq0.y - s0a.y, m0z = dg*qq0.z - s0b.x, m0w = dg*qq0.w - s0b.y;
    float m1x = dg*qq1.x - s1a.x, m1y = dg*qq1.y - s1a.y, m1z = dg*qq1.z - s1b.x, m1w = dg*qq1.w - s1b.y;

    // q_new = q + DT*(p + 0.5*DT*msg) ; p_new = p + DT*msg
    float qn0x = qq0.x + DT*(pp0.x + 0.5f*DT*m0x), qn0y = qq0.y + DT*(pp0.y + 0.5f*DT*m0y);
    float qn0z = qq0.z + DT*(pp0.z + 0.5f*DT*m0z), qn0w = qq0.w + DT*(pp0.w + 0.5f*DT*m0w);
    float qn1x = qq1.x + DT*(pp1.x + 0.5f*DT*m1x), qn1y = qq1.y + DT*(pp1.y + 0.5f*DT*m1y);
    float qn1z = qq1.z + DT*(pp1.z + 0.5f*DT*m1z), qn1w = qq1.w + DT*(pp1.w + 0.5f*DT*m1w);

    float pn0x = pp0.x + DT*m0x, pn0y = pp0.y + DT*m0y, pn0z = pp0.z + DT*m0z, pn0w = pp0.w + DT*m0w;
    float pn1x = pp1.x + DT*m1x, pn1y = pp1.y + DT*m1y, pn1z = pp1.z + DT*m1z, pn1w = pp1.w + DT*m1w;

    if (n == 0) {
        const float4* obs4 = reinterpret_cast<const float4*>(obs);
        const float4* kg4  = reinterpret_cast<const float4*>(kg);
        float4 ob0 = obs4[c];          // observations[0]
        float4 ob1 = obs4[16 + c];     // observations[1]
        float4 kq  = kg4[c];           // kalman_gain[0:D]
        float4 kp  = kg4[16 + c];      // kalman_gain[D:2D]

        float i0x = ob0.x-qn0x, i0y = ob0.y-qn0y, i0z = ob0.z-qn0z, i0w = ob0.w-qn0w;
        float i1x = ob1.x-qn1x, i1y = ob1.y-qn1y, i1z = ob1.z-qn1z, i1w = ob1.w-qn1w;
        qn0x += kq.x*i0x; qn0y += kq.y*i0y; qn0z += kq.z*i0z; qn0w += kq.w*i0w;
        qn1x += kq.x*i1x; qn1y += kq.y*i1y; qn1z += kq.z*i1z; qn1w += kq.w*i1w;
        pn0x += kp.x*i0x; pn0y += kp.y*i0y; pn0z += kp.z*i0z; pn0w += kp.w*i0w;
        pn1x += kp.x*i1x; pn1y += kp.y*i1y; pn1z += kp.z*i1z; pn1w += kp.w*i1w;
    }

    float4* o4 = reinterpret_cast<float4*>(out);
    __stcs(&o4[i0],        make_float4(qn0x, qn0y, qn0z, qn0w));   // q_new batch 0
    __stcs(&o4[i1],        make_float4(qn1x, qn1y, qn1z, qn1w));   // q_new batch 1
    __stcs(&o4[TOT4 + i0], make_float4(pn0x, pn0y, pn0z, pn0w));   // p_new batch 0
    __stcs(&o4[TOT4 + i1], make_float4(pn1x, pn1y, pn1z, pn1w));   // p_new batch 1
}

extern "C" void kernel_launch(void* const* d_in, const int* in_sizes, int n_in,
                              void* d_out, int out_size) {
    const float* q   = (const float*)d_in[0];   // node_q  (B,N,D) f32
    const float* p   = (const float*)d_in[1];   // node_p  (B,N,D) f32
    const float* obs = (const float*)d_in[2];   // observations (B,D) f32
    const float* kg  = (const float*)d_in[3];   // kalman_gain (2D,) f32
    const int2*  edg = (const int2*)d_in[4];    // edges (E,2) i32
    float* out = (float*)d_out;

    edge_kernel<<<(E * 16 + 255) / 256, 256>>>(edg, q);
    finalize_kernel<<<(ND4 + 255) / 256, 256>>>(q, p, obs, kg, out);
}